// round 16
// baseline (speedup 1.0000x reference)
#include <cuda_runtime.h>
#include <cuda_fp16.h>
#include <stdint.h>

#define B_  32
#define S_  512
#define D_  2048
#define MTOT (B_*S_)          // 16384 rows
#define NTILES 16             // 2048/128 n-tiles

// ---------------- device scratch (no allocations allowed) ----------------
__device__ __align__(16) __half g_xh   [(size_t)MTOT * D_];   // 64 MiB fp16 x [m][k]
__device__ __align__(16) __half g_w1t  [(size_t)D_ * D_];     //  8 MiB fp16 W1^T [n][k]
__device__ __align__(16) float  g_vpart[NTILES * MTOT];       // partial v
__device__ __align__(16) float2 g_G    [MTOT];                // Green diag (re,im)

// ---------------- PTX helpers ----------------
__device__ __forceinline__ uint32_t smem_u32(const void* p){
    return (uint32_t)__cvta_generic_to_shared(p);
}
__device__ __forceinline__ void cp16(void* s, const void* g){
    asm volatile("cp.async.cg.shared.global [%0], [%1], 16;\n"
                 :: "r"(smem_u32(s)), "l"(g));
}
__device__ __forceinline__ void cp_commit(){ asm volatile("cp.async.commit_group;\n"::); }
template<int N> __device__ __forceinline__ void cp_wait(){
    asm volatile("cp.async.wait_group %0;\n" :: "n"(N));
}
__device__ __forceinline__ void ldsm_x4(uint32_t r[4], uint32_t addr){
    asm volatile("ldmatrix.sync.aligned.m8n8.x4.shared.b16 {%0,%1,%2,%3}, [%4];\n"
                 : "=r"(r[0]), "=r"(r[1]), "=r"(r[2]), "=r"(r[3]) : "r"(addr));
}
__device__ __forceinline__ void mma16816(float c[4], const uint32_t a[4],
                                         uint32_t b0, uint32_t b1){
    asm volatile(
      "mma.sync.aligned.m16n8k16.row.col.f32.f16.f16.f32 "
      "{%0,%1,%2,%3},{%4,%5,%6,%7},{%8,%9},{%0,%1,%2,%3};\n"
      : "+f"(c[0]), "+f"(c[1]), "+f"(c[2]), "+f"(c[3])
      : "r"(a[0]), "r"(a[1]), "r"(a[2]), "r"(a[3]), "r"(b0), "r"(b1));
}
__device__ __forceinline__ float frcp(float x){
    float r; asm("rcp.approx.f32 %0, %1;" : "=f"(r) : "f"(x)); return r;
}
// PDL
__device__ __forceinline__ void grid_dep_wait(){
    asm volatile("griddepcontrol.wait;" ::: "memory");
}
__device__ __forceinline__ void grid_dep_trigger(){
    asm volatile("griddepcontrol.launch_dependents;" ::: "memory");
}

// ---------------- kernel 0: fused W1 transpose + x fp32->fp16 ----------------
// Transpose blocks FIRST (worse DRAM efficiency -> hide under the x stream).
// x path: 32B in / 16B out per thread (2x LDG.128 -> 1x STG.128 of 8 halves).
#define XB ((MTOT*(D_/8))/256)          // 16384 blocks
#define TB ((D_/32)*(D_/32))            // 4096 blocks

__global__ void prep_kernel(const float* __restrict__ x, const float* __restrict__ w1){
    if (blockIdx.x >= TB){
        int i = (blockIdx.x - TB) * 256 + threadIdx.x;     // over MTOT*D_/8
        float4 f0 = __ldcs(reinterpret_cast<const float4*>(x) + 2*i);
        float4 f1 = __ldcs(reinterpret_cast<const float4*>(x) + 2*i + 1);
        __half2 h0 = __floats2half2_rn(f0.x, f0.y);
        __half2 h1 = __floats2half2_rn(f0.z, f0.w);
        __half2 h2 = __floats2half2_rn(f1.x, f1.y);
        __half2 h3 = __floats2half2_rn(f1.z, f1.w);
        uint4 u;
        u.x = *reinterpret_cast<uint32_t*>(&h0);
        u.y = *reinterpret_cast<uint32_t*>(&h1);
        u.z = *reinterpret_cast<uint32_t*>(&h2);
        u.w = *reinterpret_cast<uint32_t*>(&h3);
        reinterpret_cast<uint4*>(g_xh)[i] = u;
        grid_dep_trigger();
    } else {
        __shared__ float t[32][33];
        int bid = blockIdx.x;
        const int bx = (bid & 63) * 32;      // n tile
        const int by = (bid >> 6) * 32;      // k tile
        const int tx = threadIdx.x & 31;
        const int ty = threadIdx.x >> 5;     // 0..7
        #pragma unroll
        for (int i = ty; i < 32; i += 8)
            t[i][tx] = __ldcs(w1 + (size_t)(by + i) * D_ + bx + tx);
        __syncthreads();
        #pragma unroll
        for (int i = ty; i < 32; i += 8)
            g_w1t[(size_t)(bx + i) * D_ + by + tx] = __float2half_rn(t[tx][i]);
        grid_dep_trigger();
    }
}

// ---------------- kernel 1: HMMA GEMM tile 128x128, warp 64x32 -----------------
// grid = (16 n-tiles, 128 m-tiles); 256 threads = 8 warps as 2(m) x 4(n).
// 3-stage cp.async pipeline, K chunk = 64; register double-buffered fragments.
// Legacy-path frontier: crossbar(ldsm) + HMMA pipe sum-bound — frozen.
#define AP 72                    // padded row stride in halves (64+8)
#define TILE_HALF (128*AP)       // halves per (A or B) tile per stage
#define STG_HALF  (2*TILE_HALF)
#define NSTG 3
#define SMEM_BYTES (NSTG*STG_HALF*2 + 128*4*4)
#define NK 32                    // 2048/64 k-chunks

__global__ void __launch_bounds__(256, 2)
gemm_v_kernel(const float* __restrict__ b1, const float* __restrict__ w2)
{
    extern __shared__ char smem_raw[];
    __half* sm = reinterpret_cast<__half*>(smem_raw);               // [3][2][128][AP]
    float*  vsm = reinterpret_cast<float*>(smem_raw + NSTG*STG_HALF*2);  // [128][4]

    const int tid  = threadIdx.x;
    const int lane = tid & 31;
    const int warp = tid >> 5;
    const int wm   = warp >> 2;     // 0..1
    const int wn   = warp & 3;      // 0..3
    const int nb    = blockIdx.x * 128;
    const size_t mbase = (size_t)blockIdx.y * 128;

    const __half* Ag = g_xh  + mbase * D_;
    const __half* Bg = g_w1t + (size_t)nb * D_;

    auto load_stage = [&](int s, int kt){
        __half* sa = sm + s * STG_HALF;
        __half* sb = sa + TILE_HALF;
        #pragma unroll
        for (int i = 0; i < 4; i++){
            int id = tid + i * 256;
            int r = id >> 3, c = id & 7;
            cp16(sa + r*AP + c*8, Ag + (size_t)r*D_ + kt*64 + c*8);
        }
        #pragma unroll
        for (int i = 0; i < 4; i++){
            int id = tid + i * 256;
            int r = id >> 3, c = id & 7;
            cp16(sb + r*AP + c*8, Bg + (size_t)r*D_ + kt*64 + c*8);
        }
    };

    float acc[4][4][4];
    #pragma unroll
    for (int mi = 0; mi < 4; mi++)
        #pragma unroll
        for (int j = 0; j < 4; j++)
            #pragma unroll
            for (int r = 0; r < 4; r++) acc[mi][j][r] = 0.0f;

    grid_dep_wait();               // prep must have produced g_xh / g_w1t

    load_stage(0, 0); cp_commit();
    load_stage(1, 1); cp_commit();

    const int lrow = lane & 15;
    const int lcol = (lane >> 4) * 8;
    const int arow = (wm*64 + lrow) * AP + lcol;   // + mi*16*AP + ks*16
    const int brow = (wn*32 + lrow) * AP + lcol;   // + bg*16*AP + ks*16

    uint32_t af[2][4][4], bf[2][2][4];

    auto load_frags = [&](const __half* sa, const __half* sb, int ks, int buf){
        #pragma unroll
        for (int mi = 0; mi < 4; mi++)
            ldsm_x4(af[buf][mi], smem_u32(sa + arow + mi*16*AP + ks*16));
        #pragma unroll
        for (int bg = 0; bg < 2; bg++)
            ldsm_x4(bf[buf][bg], smem_u32(sb + brow + bg*16*AP + ks*16));
    };

    for (int kt = 0; kt < NK; kt++){
        if (kt < NK-1) cp_wait<1>();
        else           cp_wait<0>();
        __syncthreads();

        int s = kt % 3;
        const __half* sa = sm + s * STG_HALF;
        const __half* sb = sa + TILE_HALF;

        load_frags(sa, sb, 0, 0);

        #pragma unroll
        for (int ks = 0; ks < 4; ks++){
            const int cur = ks & 1;
            if (ks < 3) load_frags(sa, sb, ks + 1, cur ^ 1);
            #pragma unroll
            for (int mi = 0; mi < 4; mi++)
                #pragma unroll
                for (int bg = 0; bg < 2; bg++){
                    mma16816(acc[mi][bg*2+0], af[cur][mi], bf[cur][bg][0], bf[cur][bg][2]);
                    mma16816(acc[mi][bg*2+1], af[cur][mi], bf[cur][bg][1], bf[cur][bg][3]);
                }
        }

        if (kt + 2 < NK){
            int s2 = (kt + 2) % 3;     // == (kt-1)%3, released by this kt's barrier
            load_stage(s2, kt + 2);
            cp_commit();
        }
    }

    // ---------------- epilogue: bias + relu + dot(W2) partial ----------------
    #pragma unroll
    for (int mi = 0; mi < 4; mi++){
        float s0 = 0.0f, s1 = 0.0f;   // rows (lane>>2) and (lane>>2)+8
        #pragma unroll
        for (int j = 0; j < 4; j++){
            int col = nb + wn*32 + j*8 + (lane & 3)*2;
            float bb0 = b1[col], bb1 = b1[col+1];
            float ww0 = w2[col], ww1 = w2[col+1];
            s0 += fmaxf(acc[mi][j][0] + bb0, 0.0f) * ww0;
            s0 += fmaxf(acc[mi][j][1] + bb1, 0.0f) * ww1;
            s1 += fmaxf(acc[mi][j][2] + bb0, 0.0f) * ww0;
            s1 += fmaxf(acc[mi][j][3] + bb1, 0.0f) * ww1;
        }
        s0 += __shfl_xor_sync(0xffffffffu, s0, 1);
        s0 += __shfl_xor_sync(0xffffffffu, s0, 2);
        s1 += __shfl_xor_sync(0xffffffffu, s1, 1);
        s1 += __shfl_xor_sync(0xffffffffu, s1, 2);
        if ((lane & 3) == 0){
            int row = wm*64 + mi*16 + (lane >> 2);
            vsm[row*4 + wn]       = s0;
            vsm[(row + 8)*4 + wn] = s1;
        }
    }
    __syncthreads();
    if (tid < 128){
        float s = vsm[tid*4] + vsm[tid*4+1] + vsm[tid*4+2] + vsm[tid*4+3];
        g_vpart[(size_t)blockIdx.x * MTOT + mbase + tid] = s;
    }
    grid_dep_trigger();
}

// ---------------- kernel 2: Green's diagonal via parallel Mobius scan ----------
struct C2 { float x, y; };
__device__ __forceinline__ C2 cmul(C2 a, C2 b){
    return C2{ a.x*b.x - a.y*b.y, a.x*b.y + a.y*b.x };
}
__device__ __forceinline__ C2 csub(C2 a, C2 b){ return C2{a.x-b.x, a.y-b.y}; }
__device__ __forceinline__ C2 cscale(C2 a, float s){ return C2{a.x*s, a.y*s}; }

__global__ void green_kernel(const float* __restrict__ b2){
    __shared__ float  ar[S_];          // v_i - 2
    __shared__ float2 ps[S_], qs[S_];
    __shared__ C2 scanM[2][64][4];     // [group][thread][m00,m01,m10,m11]

    const int b = blockIdx.x;
    const int tid = threadIdx.x;       // 128 threads
    const int grp = tid >> 6;          // 0 = forward(p), 1 = backward(q)
    const int gt  = tid & 63;
    const float bias2 = b2[0];

    grid_dep_wait();                   // gemm must have produced g_vpart

    for (int i = tid; i < S_; i += 128){
        float s = bias2 - 2.0f;
        #pragma unroll
        for (int nt = 0; nt < NTILES; nt++)
            s += g_vpart[(size_t)nt * MTOT + b * S_ + i];
        ar[i] = s;
    }
    __syncthreads();

    // ---- local 8-step matrix product (ascending in scan direction) ----
    C2 m00{1,0}, m01{0,0}, m10{0,0}, m11{1,0};
    #pragma unroll
    for (int j = 0; j < 8; j++){
        int jl = gt*8 + j;
        int i  = grp ? (S_-1 - jl) : jl;
        C2 a{ ar[i], -1.0f };
        C2 n10 = csub(cmul(a, m10), m00);
        C2 n11 = csub(cmul(a, m11), m01);
        m00 = m10; m01 = m11; m10 = n10; m11 = n11;
    }
    {
        float nm = m10.x*m10.x + m10.y*m10.y + m11.x*m11.x + m11.y*m11.y;
        float s = rsqrtf(nm);
        m00 = cscale(m00,s); m01 = cscale(m01,s);
        m10 = cscale(m10,s); m11 = cscale(m11,s);
    }
    scanM[grp][gt][0] = m00; scanM[grp][gt][1] = m01;
    scanM[grp][gt][2] = m10; scanM[grp][gt][3] = m11;
    __syncthreads();

    // ---- inclusive scan: M[t] = M[t] * M[t-d] ----
    #pragma unroll
    for (int d = 1; d < 64; d <<= 1){
        C2 p00, p01, p10, p11;
        bool act = (gt >= d);
        if (act){
            p00 = scanM[grp][gt-d][0]; p01 = scanM[grp][gt-d][1];
            p10 = scanM[grp][gt-d][2]; p11 = scanM[grp][gt-d][3];
        }
        __syncthreads();
        if (act){
            C2 r00{ m00.x*p00.x - m00.y*p00.y + m01.x*p10.x - m01.y*p10.y,
                    m00.x*p00.y + m00.y*p00.x + m01.x*p10.y + m01.y*p10.x };
            C2 r01{ m00.x*p01.x - m00.y*p01.y + m01.x*p11.x - m01.y*p11.y,
                    m00.x*p01.y + m00.y*p01.x + m01.x*p11.y + m01.y*p11.x };
            C2 r10{ m10.x*p00.x - m10.y*p00.y + m11.x*p10.x - m11.y*p10.y,
                    m10.x*p00.y + m10.y*p00.x + m11.x*p10.y + m11.y*p10.x };
            C2 r11{ m10.x*p01.x - m10.y*p01.y + m11.x*p11.x - m11.y*p11.y,
                    m10.x*p01.y + m10.y*p01.x + m11.x*p11.y + m11.y*p11.x };
            float nm = r10.x*r10.x + r10.y*r10.y + r11.x*r11.x + r11.y*r11.y;
            float s = rsqrtf(nm);
            m00 = cscale(r00,s); m01 = cscale(r01,s);
            m10 = cscale(r10,s); m11 = cscale(r11,s);
            scanM[grp][gt][0] = m00; scanM[grp][gt][1] = m01;
            scanM[grp][gt][2] = m10; scanM[grp][gt][3] = m11;
        }
        __syncthreads();
    }

    // ---- exclusive prefix -> initial state vector; apply 8 local steps ----
    C2 u{0,0}, w{1,0};
    if (gt > 0){
        u = scanM[grp][gt-1][1];
        w = scanM[grp][gt-1][3];
    }
    #pragma unroll
    for (int j = 0; j < 8; j++){
        int jl = gt*8 + j;
        int i  = grp ? (S_-1 - jl) : jl;
        float inv = frcp(w.x*w.x + w.y*w.y);
        float2 val{ (u.x*w.x + u.y*w.y)*inv, (u.y*w.x - u.x*w.y)*inv };
        if (grp) qs[i] = val; else ps[i] = val;
        C2 a{ ar[i], -1.0f };
        C2 nw = csub(cmul(a, w), u);
        u = w; w = nw;
        float s = rsqrtf(w.x*w.x + w.y*w.y);
        u = cscale(u,s); w = cscale(w,s);
    }
    __syncthreads();

    // ---- G_ii = 1/(a_i - p_i - q_i) ----
    for (int i = tid; i < S_; i += 128){
        float wr = ar[i] - ps[i].x - qs[i].x;
        float wi = -1.0f - ps[i].y - qs[i].y;
        float inv = frcp(wr*wr + wi*wi);
        g_G[b*S_ + i] = make_float2(wr*inv, -wi*inv);
    }
    grid_dep_trigger();
}

// ---------------- kernel 3: out = Gr*Wp[0,:] + Gi*Wp[1,:] + bp ----------------
// 4 rows per thread (best measured shape); G as LDG.128; Wp/bp loaded before
// the PDL wait to overlap green's tail.
__global__ void out_kernel(const float* __restrict__ Wp, const float* __restrict__ bp,
                           float* __restrict__ out){
    int i = blockIdx.x * blockDim.x + threadIdx.x;   // over (MTOT/4)*512
    int c4   = i & 511;
    int row0 = (i >> 9) << 2;
    float4 w0 = reinterpret_cast<const float4*>(Wp)[c4];
    float4 w1 = reinterpret_cast<const float4*>(Wp + D_)[c4];
    float4 bb = reinterpret_cast<const float4*>(bp)[c4];

    grid_dep_wait();                   // green must have produced g_G

    const float4* G4 = reinterpret_cast<const float4*>(g_G);  // 2 rows per float4
    #pragma unroll
    for (int rr = 0; rr < 2; rr++){
        float4 g2 = G4[(row0 >> 1) + rr];
        #pragma unroll
        for (int h = 0; h < 2; h++){
            float gr = h ? g2.z : g2.x;
            float gi = h ? g2.w : g2.y;
            float4 o;
            o.x = gr*w0.x + gi*w1.x + bb.x;
            o.y = gr*w0.y + gi*w1.y + bb.y;
            o.z = gr*w0.z + gi*w1.z + bb.z;
            o.w = gr*w0.w + gi*w1.w + bb.w;
            __stcs(reinterpret_cast<float4*>(out) + (size_t)(row0 + rr*2 + h) * 512 + c4, o);
        }
    }
}

// ---------------- launch ----------------
static inline void launch_pdl(void* func, dim3 grid, dim3 block, size_t smem,
                              void** args){
    cudaLaunchConfig_t cfg = {};
    cfg.gridDim = grid;
    cfg.blockDim = block;
    cfg.dynamicSmemBytes = smem;
    cfg.stream = 0;
    cudaLaunchAttribute attr[1];
    attr[0].id = cudaLaunchAttributeProgrammaticStreamSerialization;
    attr[0].val.programmaticStreamSerializationAllowed = 1;
    cfg.attrs = attr;
    cfg.numAttrs = 1;
    cudaLaunchKernelExC(&cfg, func, args);
}

extern "C" void kernel_launch(void* const* d_in, const int* in_sizes, int n_in,
                              void* d_out, int out_size)
{
    const float* x  = (const float*)d_in[0];
    const float* W1 = (const float*)d_in[1];
    const float* b1 = (const float*)d_in[2];
    const float* W2 = (const float*)d_in[3];
    const float* b2 = (const float*)d_in[4];
    const float* Wp = (const float*)d_in[5];
    const float* bp = (const float*)d_in[6];
    float* out = (float*)d_out;

    prep_kernel<<<XB + TB, 256>>>(x, W1);

    cudaFuncSetAttribute(gemm_v_kernel, cudaFuncAttributeMaxDynamicSharedMemorySize, SMEM_BYTES);
    {
        void* args[] = { (void*)&b1, (void*)&W2 };
        launch_pdl((void*)gemm_v_kernel, dim3(NTILES, MTOT/128), dim3(256), SMEM_BYTES, args);
    }
    {
        void* args[] = { (void*)&b2 };
        launch_pdl((void*)green_kernel, dim3(B_), dim3(128), 0, args);
    }
    {
        void* args[] = { (void*)&Wp, (void*)&bp, (void*)&out };
        launch_pdl((void*)out_kernel, dim3((MTOT/4*512)/256), dim3(256), 0, args);
    }
}

// round 17
// speedup vs baseline: 1.0026x; 1.0026x over previous
#include <cuda_runtime.h>
#include <cuda_fp16.h>
#include <stdint.h>

#define B_  32
#define S_  512
#define D_  2048
#define MTOT (B_*S_)          // 16384 rows
#define NTILES 16             // 2048/128 n-tiles

// ---------------- device scratch (no allocations allowed) ----------------
__device__ __align__(16) __half g_xh   [(size_t)MTOT * D_];   // 64 MiB fp16 x [m][k]
__device__ __align__(16) __half g_w1t  [(size_t)D_ * D_];     //  8 MiB fp16 W1^T [n][k]
__device__ __align__(16) float  g_vpart[NTILES * MTOT];       // partial v
__device__ __align__(16) float2 g_G    [MTOT];                // Green diag (re,im)

// ---------------- PTX helpers ----------------
__device__ __forceinline__ uint32_t smem_u32(const void* p){
    return (uint32_t)__cvta_generic_to_shared(p);
}
__device__ __forceinline__ void cp16(void* s, const void* g){
    asm volatile("cp.async.cg.shared.global [%0], [%1], 16;\n"
                 :: "r"(smem_u32(s)), "l"(g));
}
__device__ __forceinline__ void cp_commit(){ asm volatile("cp.async.commit_group;\n"::); }
template<int N> __device__ __forceinline__ void cp_wait(){
    asm volatile("cp.async.wait_group %0;\n" :: "n"(N));
}
__device__ __forceinline__ void ldsm_x4(uint32_t r[4], uint32_t addr){
    asm volatile("ldmatrix.sync.aligned.m8n8.x4.shared.b16 {%0,%1,%2,%3}, [%4];\n"
                 : "=r"(r[0]), "=r"(r[1]), "=r"(r[2]), "=r"(r[3]) : "r"(addr));
}
__device__ __forceinline__ void mma16816(float c[4], const uint32_t a[4],
                                         uint32_t b0, uint32_t b1){
    asm volatile(
      "mma.sync.aligned.m16n8k16.row.col.f32.f16.f16.f32 "
      "{%0,%1,%2,%3},{%4,%5,%6,%7},{%8,%9},{%0,%1,%2,%3};\n"
      : "+f"(c[0]), "+f"(c[1]), "+f"(c[2]), "+f"(c[3])
      : "r"(a[0]), "r"(a[1]), "r"(a[2]), "r"(a[3]), "r"(b0), "r"(b1));
}
__device__ __forceinline__ float frcp(float x){
    float r; asm("rcp.approx.f32 %0, %1;" : "=f"(r) : "f"(x)); return r;
}
// PDL
__device__ __forceinline__ void grid_dep_wait(){
    asm volatile("griddepcontrol.wait;" ::: "memory");
}

// ---------------- kernel 0: fused W1 transpose + x fp32->fp16 ----------------
// Transpose blocks FIRST (worse DRAM efficiency -> hide under the x stream).
// x path: 32B in / 16B out per thread (2x LDG.128 -> 1x STG.128 of 8 halves).
#define XB ((MTOT*(D_/8))/256)          // 16384 blocks
#define TB ((D_/32)*(D_/32))            // 4096 blocks

__global__ void prep_kernel(const float* __restrict__ x, const float* __restrict__ w1){
    if (blockIdx.x >= TB){
        int i = (blockIdx.x - TB) * 256 + threadIdx.x;     // over MTOT*D_/8
        float4 f0 = __ldcs(reinterpret_cast<const float4*>(x) + 2*i);
        float4 f1 = __ldcs(reinterpret_cast<const float4*>(x) + 2*i + 1);
        __half2 h0 = __floats2half2_rn(f0.x, f0.y);
        __half2 h1 = __floats2half2_rn(f0.z, f0.w);
        __half2 h2 = __floats2half2_rn(f1.x, f1.y);
        __half2 h3 = __floats2half2_rn(f1.z, f1.w);
        uint4 u;
        u.x = *reinterpret_cast<uint32_t*>(&h0);
        u.y = *reinterpret_cast<uint32_t*>(&h1);
        u.z = *reinterpret_cast<uint32_t*>(&h2);
        u.w = *reinterpret_cast<uint32_t*>(&h3);
        reinterpret_cast<uint4*>(g_xh)[i] = u;
    } else {
        __shared__ float t[32][33];
        int bid = blockIdx.x;
        const int bx = (bid & 63) * 32;      // n tile
        const int by = (bid >> 6) * 32;      // k tile
        const int tx = threadIdx.x & 31;
        const int ty = threadIdx.x >> 5;     // 0..7
        #pragma unroll
        for (int i = ty; i < 32; i += 8)
            t[i][tx] = __ldcs(w1 + (size_t)(by + i) * D_ + bx + tx);
        __syncthreads();
        #pragma unroll
        for (int i = ty; i < 32; i += 8)
            g_w1t[(size_t)(bx + i) * D_ + by + tx] = __float2half_rn(t[tx][i]);
    }
}

// ---------------- kernel 1: HMMA GEMM tile 128x128, warp 64x32 -----------------
// grid = (16 n-tiles, 128 m-tiles); 256 threads = 8 warps as 2(m) x 4(n).
// 3-stage cp.async pipeline, K chunk = 64; register double-buffered fragments.
// Legacy-path frontier: crossbar(ldsm) + HMMA pipe sum-bound — frozen.
#define AP 72                    // padded row stride in halves (64+8)
#define TILE_HALF (128*AP)       // halves per (A or B) tile per stage
#define STG_HALF  (2*TILE_HALF)
#define NSTG 3
#define SMEM_BYTES (NSTG*STG_HALF*2 + 128*4*4)
#define NK 32                    // 2048/64 k-chunks

__global__ void __launch_bounds__(256, 2)
gemm_v_kernel(const float* __restrict__ b1, const float* __restrict__ w2)
{
    extern __shared__ char smem_raw[];
    __half* sm = reinterpret_cast<__half*>(smem_raw);               // [3][2][128][AP]
    float*  vsm = reinterpret_cast<float*>(smem_raw + NSTG*STG_HALF*2);  // [128][4]

    const int tid  = threadIdx.x;
    const int lane = tid & 31;
    const int warp = tid >> 5;
    const int wm   = warp >> 2;     // 0..1
    const int wn   = warp & 3;      // 0..3
    const int nb    = blockIdx.x * 128;
    const size_t mbase = (size_t)blockIdx.y * 128;

    const __half* Ag = g_xh  + mbase * D_;
    const __half* Bg = g_w1t + (size_t)nb * D_;

    auto load_stage = [&](int s, int kt){
        __half* sa = sm + s * STG_HALF;
        __half* sb = sa + TILE_HALF;
        #pragma unroll
        for (int i = 0; i < 4; i++){
            int id = tid + i * 256;
            int r = id >> 3, c = id & 7;
            cp16(sa + r*AP + c*8, Ag + (size_t)r*D_ + kt*64 + c*8);
        }
        #pragma unroll
        for (int i = 0; i < 4; i++){
            int id = tid + i * 256;
            int r = id >> 3, c = id & 7;
            cp16(sb + r*AP + c*8, Bg + (size_t)r*D_ + kt*64 + c*8);
        }
    };

    float acc[4][4][4];
    #pragma unroll
    for (int mi = 0; mi < 4; mi++)
        #pragma unroll
        for (int j = 0; j < 4; j++)
            #pragma unroll
            for (int r = 0; r < 4; r++) acc[mi][j][r] = 0.0f;

    grid_dep_wait();               // prep must have produced g_xh / g_w1t

    load_stage(0, 0); cp_commit();
    load_stage(1, 1); cp_commit();

    const int lrow = lane & 15;
    const int lcol = (lane >> 4) * 8;
    const int arow = (wm*64 + lrow) * AP + lcol;   // + mi*16*AP + ks*16
    const int brow = (wn*32 + lrow) * AP + lcol;   // + bg*16*AP + ks*16

    uint32_t af[2][4][4], bf[2][2][4];

    auto load_frags = [&](const __half* sa, const __half* sb, int ks, int buf){
        #pragma unroll
        for (int mi = 0; mi < 4; mi++)
            ldsm_x4(af[buf][mi], smem_u32(sa + arow + mi*16*AP + ks*16));
        #pragma unroll
        for (int bg = 0; bg < 2; bg++)
            ldsm_x4(bf[buf][bg], smem_u32(sb + brow + bg*16*AP + ks*16));
    };

    for (int kt = 0; kt < NK; kt++){
        if (kt < NK-1) cp_wait<1>();
        else           cp_wait<0>();
        __syncthreads();

        int s = kt % 3;
        const __half* sa = sm + s * STG_HALF;
        const __half* sb = sa + TILE_HALF;

        load_frags(sa, sb, 0, 0);

        #pragma unroll
        for (int ks = 0; ks < 4; ks++){
            const int cur = ks & 1;
            if (ks < 3) load_frags(sa, sb, ks + 1, cur ^ 1);
            #pragma unroll
            for (int mi = 0; mi < 4; mi++)
                #pragma unroll
                for (int bg = 0; bg < 2; bg++){
                    mma16816(acc[mi][bg*2+0], af[cur][mi], bf[cur][bg][0], bf[cur][bg][2]);
                    mma16816(acc[mi][bg*2+1], af[cur][mi], bf[cur][bg][1], bf[cur][bg][3]);
                }
        }

        if (kt + 2 < NK){
            int s2 = (kt + 2) % 3;     // == (kt-1)%3, released by this kt's barrier
            load_stage(s2, kt + 2);
            cp_commit();
        }
    }

    // ---------------- epilogue: bias + relu + dot(W2) partial ----------------
    #pragma unroll
    for (int mi = 0; mi < 4; mi++){
        float s0 = 0.0f, s1 = 0.0f;   // rows (lane>>2) and (lane>>2)+8
        #pragma unroll
        for (int j = 0; j < 4; j++){
            int col = nb + wn*32 + j*8 + (lane & 3)*2;
            float bb0 = b1[col], bb1 = b1[col+1];
            float ww0 = w2[col], ww1 = w2[col+1];
            s0 += fmaxf(acc[mi][j][0] + bb0, 0.0f) * ww0;
            s0 += fmaxf(acc[mi][j][1] + bb1, 0.0f) * ww1;
            s1 += fmaxf(acc[mi][j][2] + bb0, 0.0f) * ww0;
            s1 += fmaxf(acc[mi][j][3] + bb1, 0.0f) * ww1;
        }
        s0 += __shfl_xor_sync(0xffffffffu, s0, 1);
        s0 += __shfl_xor_sync(0xffffffffu, s0, 2);
        s1 += __shfl_xor_sync(0xffffffffu, s1, 1);
        s1 += __shfl_xor_sync(0xffffffffu, s1, 2);
        if ((lane & 3) == 0){
            int row = wm*64 + mi*16 + (lane >> 2);
            vsm[row*4 + wn]       = s0;
            vsm[(row + 8)*4 + wn] = s1;
        }
    }
    __syncthreads();
    if (tid < 128){
        float s = vsm[tid*4] + vsm[tid*4+1] + vsm[tid*4+2] + vsm[tid*4+3];
        g_vpart[(size_t)blockIdx.x * MTOT + mbase + tid] = s;
    }
}

// ---------------- kernel 2: Green's diagonal via parallel Mobius scan ----------
// 256 threads: float4-vectorized v-reduction (threads 0..127 handle 4 rows each),
// then the verified 128-thread Mobius scan.
struct C2 { float x, y; };
__device__ __forceinline__ C2 cmul(C2 a, C2 b){
    return C2{ a.x*b.x - a.y*b.y, a.x*b.y + a.y*b.x };
}
__device__ __forceinline__ C2 csub(C2 a, C2 b){ return C2{a.x-b.x, a.y-b.y}; }
__device__ __forceinline__ C2 cscale(C2 a, float s){ return C2{a.x*s, a.y*s}; }

__global__ void green_kernel(const float* __restrict__ b2){
    __shared__ float  ar[S_];          // v_i - 2
    __shared__ float2 ps[S_], qs[S_];
    __shared__ C2 scanM[2][64][4];     // [group][thread][m00,m01,m10,m11]

    const int b = blockIdx.x;
    const int tid = threadIdx.x;       // 256 threads
    const float bias2 = b2[0];

    grid_dep_wait();                   // gemm must have produced g_vpart

    // ---- v reduction: one float4 (4 rows) per thread, LDG.128 per partial ----
    if (tid < S_/4){
        float4 s = make_float4(bias2 - 2.0f, bias2 - 2.0f, bias2 - 2.0f, bias2 - 2.0f);
        #pragma unroll
        for (int nt = 0; nt < NTILES; nt++){
            float4 p = *reinterpret_cast<const float4*>(
                g_vpart + (size_t)nt * MTOT + b * S_ + tid * 4);
            s.x += p.x; s.y += p.y; s.z += p.z; s.w += p.w;
        }
        reinterpret_cast<float4*>(ar)[tid] = s;
    }
    __syncthreads();

    if (tid < 128){
        const int grp = tid >> 6;      // 0 = forward(p), 1 = backward(q)
        const int gt  = tid & 63;

        // ---- local 8-step matrix product (ascending in scan direction) ----
        C2 m00{1,0}, m01{0,0}, m10{0,0}, m11{1,0};
        #pragma unroll
        for (int j = 0; j < 8; j++){
            int jl = gt*8 + j;
            int i  = grp ? (S_-1 - jl) : jl;
            C2 a{ ar[i], -1.0f };
            C2 n10 = csub(cmul(a, m10), m00);
            C2 n11 = csub(cmul(a, m11), m01);
            m00 = m10; m01 = m11; m10 = n10; m11 = n11;
        }
        {
            float nm = m10.x*m10.x + m10.y*m10.y + m11.x*m11.x + m11.y*m11.y;
            float s = rsqrtf(nm);
            m00 = cscale(m00,s); m01 = cscale(m01,s);
            m10 = cscale(m10,s); m11 = cscale(m11,s);
        }
        scanM[grp][gt][0] = m00; scanM[grp][gt][1] = m01;
        scanM[grp][gt][2] = m10; scanM[grp][gt][3] = m11;
        asm volatile("bar.sync 1, 128;" ::: "memory");

        // ---- inclusive scan: M[t] = M[t] * M[t-d] ----
        #pragma unroll
        for (int d = 1; d < 64; d <<= 1){
            C2 p00, p01, p10, p11;
            bool act = (gt >= d);
            if (act){
                p00 = scanM[grp][gt-d][0]; p01 = scanM[grp][gt-d][1];
                p10 = scanM[grp][gt-d][2]; p11 = scanM[grp][gt-d][3];
            }
            asm volatile("bar.sync 1, 128;" ::: "memory");
            if (act){
                C2 r00{ m00.x*p00.x - m00.y*p00.y + m01.x*p10.x - m01.y*p10.y,
                        m00.x*p00.y + m00.y*p00.x + m01.x*p10.y + m01.y*p10.x };
                C2 r01{ m00.x*p01.x - m00.y*p01.y + m01.x*p11.x - m01.y*p11.y,
                        m00.x*p01.y + m00.y*p01.x + m01.x*p11.y + m01.y*p11.x };
                C2 r10{ m10.x*p00.x - m10.y*p00.y + m11.x*p10.x - m11.y*p10.y,
                        m10.x*p00.y + m10.y*p00.x + m11.x*p10.y + m11.y*p10.x };
                C2 r11{ m10.x*p01.x - m10.y*p01.y + m11.x*p11.x - m11.y*p11.y,
                        m10.x*p01.y + m10.y*p01.x + m11.x*p11.y + m11.y*p11.x };
                float nm = r10.x*r10.x + r10.y*r10.y + r11.x*r11.x + r11.y*r11.y;
                float s = rsqrtf(nm);
                m00 = cscale(r00,s); m01 = cscale(r01,s);
                m10 = cscale(r10,s); m11 = cscale(r11,s);
                scanM[grp][gt][0] = m00; scanM[grp][gt][1] = m01;
                scanM[grp][gt][2] = m10; scanM[grp][gt][3] = m11;
            }
            asm volatile("bar.sync 1, 128;" ::: "memory");
        }

        // ---- exclusive prefix -> initial state vector; apply 8 local steps ----
        C2 u{0,0}, w{1,0};
        if (gt > 0){
            u = scanM[grp][gt-1][1];
            w = scanM[grp][gt-1][3];
        }
        #pragma unroll
        for (int j = 0; j < 8; j++){
            int jl = gt*8 + j;
            int i  = grp ? (S_-1 - jl) : jl;
            float inv = frcp(w.x*w.x + w.y*w.y);
            float2 val{ (u.x*w.x + u.y*w.y)*inv, (u.y*w.x - u.x*w.y)*inv };
            if (grp) qs[i] = val; else ps[i] = val;
            C2 a{ ar[i], -1.0f };
            C2 nw = csub(cmul(a, w), u);
            u = w; w = nw;
            float s = rsqrtf(w.x*w.x + w.y*w.y);
            u = cscale(u,s); w = cscale(w,s);
        }
    }
    __syncthreads();

    // ---- G_ii = 1/(a_i - p_i - q_i) (all 256 threads) ----
    for (int i = tid; i < S_; i += 256){
        float wr = ar[i] - ps[i].x - qs[i].x;
        float wi = -1.0f - ps[i].y - qs[i].y;
        float inv = frcp(wr*wr + wi*wi);
        g_G[b*S_ + i] = make_float2(wr*inv, -wi*inv);
    }
}

// ---------------- kernel 3: out = Gr*Wp[0,:] + Gi*Wp[1,:] + bp ----------------
// 4 rows per thread (best measured shape); G as LDG.128; Wp/bp loaded before
// the PDL wait to overlap green's tail.
__global__ void out_kernel(const float* __restrict__ Wp, const float* __restrict__ bp,
                           float* __restrict__ out){
    int i = blockIdx.x * blockDim.x + threadIdx.x;   // over (MTOT/4)*512
    int c4   = i & 511;
    int row0 = (i >> 9) << 2;
    float4 w0 = reinterpret_cast<const float4*>(Wp)[c4];
    float4 w1 = reinterpret_cast<const float4*>(Wp + D_)[c4];
    float4 bb = reinterpret_cast<const float4*>(bp)[c4];

    grid_dep_wait();                   // green must have produced g_G

    const float4* G4 = reinterpret_cast<const float4*>(g_G);  // 2 rows per float4
    #pragma unroll
    for (int rr = 0; rr < 2; rr++){
        float4 g2 = G4[(row0 >> 1) + rr];
        #pragma unroll
        for (int h = 0; h < 2; h++){
            float gr = h ? g2.z : g2.x;
            float gi = h ? g2.w : g2.y;
            float4 o;
            o.x = gr*w0.x + gi*w1.x + bb.x;
            o.y = gr*w0.y + gi*w1.y + bb.y;
            o.z = gr*w0.z + gi*w1.z + bb.z;
            o.w = gr*w0.w + gi*w1.w + bb.w;
            __stcs(reinterpret_cast<float4*>(out) + (size_t)(row0 + rr*2 + h) * 512 + c4, o);
        }
    }
}

// ---------------- launch ----------------
static inline void launch_pdl(void* func, dim3 grid, dim3 block, size_t smem,
                              void** args){
    cudaLaunchConfig_t cfg = {};
    cfg.gridDim = grid;
    cfg.blockDim = block;
    cfg.dynamicSmemBytes = smem;
    cfg.stream = 0;
    cudaLaunchAttribute attr[1];
    attr[0].id = cudaLaunchAttributeProgrammaticStreamSerialization;
    attr[0].val.programmaticStreamSerializationAllowed = 1;
    cfg.attrs = attr;
    cfg.numAttrs = 1;
    cudaLaunchKernelExC(&cfg, func, args);
}

extern "C" void kernel_launch(void* const* d_in, const int* in_sizes, int n_in,
                              void* d_out, int out_size)
{
    const float* x  = (const float*)d_in[0];
    const float* W1 = (const float*)d_in[1];
    const float* b1 = (const float*)d_in[2];
    const float* W2 = (const float*)d_in[3];
    const float* b2 = (const float*)d_in[4];
    const float* Wp = (const float*)d_in[5];
    const float* bp = (const float*)d_in[6];
    float* out = (float*)d_out;

    prep_kernel<<<XB + TB, 256>>>(x, W1);

    cudaFuncSetAttribute(gemm_v_kernel, cudaFuncAttributeMaxDynamicSharedMemorySize, SMEM_BYTES);
    {
        void* args[] = { (void*)&b1, (void*)&W2 };
        launch_pdl((void*)gemm_v_kernel, dim3(NTILES, MTOT/128), dim3(256), SMEM_BYTES, args);
    }
    {
        void* args[] = { (void*)&b2 };
        launch_pdl((void*)green_kernel, dim3(B_), dim3(256), 0, args);
    }
    {
        void* args[] = { (void*)&Wp, (void*)&bp, (void*)&out };
        launch_pdl((void*)out_kernel, dim3((MTOT/4*512)/256), dim3(256), 0, args);
    }
}